// round 1
// baseline (speedup 1.0000x reference)
#include <cuda_runtime.h>

// adder2d (AdderNet) SAD-convolution, fully on-device:
//   1) k_scale : per-tensor symmetric quant scale from max|W|
//   2) k_quant : W_clip (transposed k-major -> g_Wt[k][m]) + per-filter bias
//   3) k_main  : direct-conv SAD, block = (batch b, output row h) x all 128 filters
//
// Shapes (fixed by problem): x (32,64,32,32) f32, W (128,64,3,3) f32, bits=8 (int32)
// out (32,128,32,32) f32

#define C_IN   64
#define H_IN   32
#define W_IN   32
#define M_OUT  128
#define KK     (C_IN * 9)   // 576
#define BATCH  32
#define CB     4            // channels per smem chunk in main kernel

__device__ float g_scale;
__device__ float g_qmin;
__device__ float g_qmax;
__device__ __align__(16) float g_Wt[KK * M_OUT];   // k-major, m contiguous
__device__ float g_bias[M_OUT];

// ---------------------------------------------------------------------------
// K0: alpha = max|W|, scale = max(alpha/qmax, 1e-6). Single block.
// ---------------------------------------------------------------------------
__global__ void k_scale(const float* __restrict__ W, const int* __restrict__ bits_p) {
    __shared__ float red[32];
    float m = 0.f;
    for (int i = threadIdx.x; i < M_OUT * KK; i += 1024)
        m = fmaxf(m, fabsf(W[i]));
    #pragma unroll
    for (int o = 16; o; o >>= 1) m = fmaxf(m, __shfl_xor_sync(0xffffffffu, m, o));
    if ((threadIdx.x & 31) == 0) red[threadIdx.x >> 5] = m;
    __syncthreads();
    if (threadIdx.x < 32) {
        float v = red[threadIdx.x];
        #pragma unroll
        for (int o = 16; o; o >>= 1) v = fmaxf(v, __shfl_xor_sync(0xffffffffu, v, o));
        if (threadIdx.x == 0) {
            int bits = *bits_p;
            float qmax = (float)((1 << (bits - 1)) - 1);
            g_scale = fmaxf(v / qmax, 1e-6f);
            g_qmax  = qmax;
            g_qmin  = -(float)(1 << (bits - 1));
        }
    }
}

// ---------------------------------------------------------------------------
// K1: quantize W, write transposed g_Wt[k*128+m], bias[m] = -sum_k |W - Wclip|
// One block per output filter m.
// ---------------------------------------------------------------------------
__global__ void k_quant(const float* __restrict__ W) {
    const int m = blockIdx.x;
    const float s   = g_scale;
    const float qmx = g_qmax;
    const float qmn = g_qmin;
    float sum = 0.f;
    for (int k = threadIdx.x; k < KK; k += blockDim.x) {
        float w  = W[m * KK + k];
        float q  = rintf(w / s);              // round half-to-even, matches jnp.round
        q        = fminf(fmaxf(q, qmn), qmx);
        float wc = q * s;
        g_Wt[k * M_OUT + m] = wc;
        sum += fabsf(w - wc);
    }
    __shared__ float red[8];
    #pragma unroll
    for (int o = 16; o; o >>= 1) sum += __shfl_xor_sync(0xffffffffu, sum, o);
    if ((threadIdx.x & 31) == 0) red[threadIdx.x >> 5] = sum;
    __syncthreads();
    if (threadIdx.x == 0) {
        float t = 0.f;
        #pragma unroll
        for (int i = 0; i < 8; i++) t += red[i];
        g_bias[m] = -t;
    }
}

// ---------------------------------------------------------------------------
// K2: main SAD kernel.
// grid = (H_IN, BATCH) = 1024 blocks, 128 threads each.
// thread (tm = tid>>3, tp = tid&7): m in [tm*8, tm*8+8), w in [tp*4, tp*4+4)
// smem: W slice (CB*9 k-rows x 128 m) + haloed x slice (CB ch x 3 rows x 34 cols)
// ---------------------------------------------------------------------------
__global__ void __launch_bounds__(128)
k_main(const float* __restrict__ x, float* __restrict__ out) {
    __shared__ __align__(16) float sW[CB * 9][M_OUT];
    __shared__ float sX[CB][3][34];

    const int h0  = blockIdx.x;
    const int b   = blockIdx.y;
    const int tid = threadIdx.x;
    const int tm  = tid >> 3;    // 0..15
    const int tp  = tid & 7;     // 0..7
    const int m0  = tm * 8;
    const int w0  = tp * 4;

    float acc[8][4];
    #pragma unroll
    for (int i = 0; i < 8; i++)
        #pragma unroll
        for (int j = 0; j < 4; j++) acc[i][j] = 0.f;

    const float* xb = x + (size_t)b * C_IN * H_IN * W_IN;

    for (int c0 = 0; c0 < C_IN; c0 += CB) {
        // --- load W chunk: CB*9 rows x 128 floats = 1152 float4, 9 per thread
        {
            const float4* gw  = (const float4*)(g_Wt + c0 * 9 * M_OUT);
            float4*       sw4 = (float4*)(&sW[0][0]);
            #pragma unroll
            for (int i = 0; i < (CB * 9 * M_OUT / 4) / 128; i++)
                sw4[tid + i * 128] = gw[tid + i * 128];
        }
        // --- load haloed x chunk: CB x 3 x 34 = 408 floats (zero-padded)
        for (int idx = tid; idx < CB * 3 * 34; idx += 128) {
            int ci  = idx / 102;
            int r   = idx - ci * 102;
            int dh  = r / 34;
            int cc  = r - dh * 34;
            int row = h0 + dh - 1;
            int col = cc - 1;
            float v = 0.f;
            if ((unsigned)row < H_IN && (unsigned)col < W_IN)
                v = xb[((c0 + ci) * H_IN + row) * W_IN + col];
            sX[ci][dh][cc] = v;
        }
        __syncthreads();

        #pragma unroll 1   // keep body ~one channel to stay inside I$ L1.5
        for (int ci = 0; ci < CB; ci++) {
            // per-channel x registers: 3 rows x 6 cols (covers all 9 taps, 4 w's)
            float xr[3][6];
            #pragma unroll
            for (int dh = 0; dh < 3; dh++)
                #pragma unroll
                for (int j = 0; j < 6; j++)
                    xr[dh][j] = sX[ci][dh][w0 + j];

            #pragma unroll
            for (int t = 0; t < 9; t++) {
                const int dh = t / 3;
                const int dw = t - dh * 3;
                float wv[8];
                float4 wa = *(const float4*)(&sW[ci * 9 + t][m0]);
                float4 wb = *(const float4*)(&sW[ci * 9 + t][m0 + 4]);
                wv[0] = wa.x; wv[1] = wa.y; wv[2] = wa.z; wv[3] = wa.w;
                wv[4] = wb.x; wv[5] = wb.y; wv[6] = wb.z; wv[7] = wb.w;
                #pragma unroll
                for (int i = 0; i < 8; i++)
                    #pragma unroll
                    for (int j = 0; j < 4; j++)
                        acc[i][j] += fabsf(wv[i] - xr[dh][dw + j]);
            }
        }
        __syncthreads();
    }

    // epilogue: out[b][m][h0][w0..w0+3] = bias[m] - acc
    #pragma unroll
    for (int i = 0; i < 8; i++) {
        float bv = g_bias[m0 + i];
        float4 o;
        o.x = bv - acc[i][0];
        o.y = bv - acc[i][1];
        o.z = bv - acc[i][2];
        o.w = bv - acc[i][3];
        *(float4*)(out + (((size_t)b * M_OUT + (m0 + i)) * H_IN + h0) * W_IN + w0) = o;
    }
}

// ---------------------------------------------------------------------------
extern "C" void kernel_launch(void* const* d_in, const int* in_sizes, int n_in,
                              void* d_out, int out_size) {
    const float* x    = (const float*)d_in[0];
    const float* W    = (const float*)d_in[1];
    const int*   bits = (const int*)d_in[2];
    float*       out  = (float*)d_out;

    k_scale<<<1, 1024>>>(W, bits);
    k_quant<<<M_OUT, 256>>>(W);
    dim3 grid(H_IN, BATCH);
    k_main<<<grid, 128>>>(x, out);
}

// round 2
// speedup vs baseline: 1.0911x; 1.0911x over previous
#include <cuda_runtime.h>
#include <cuda_fp16.h>

// AdderNet SAD-conv, fp16x2-packed inner loop (pack along M, broadcast x).
//   k_init  : zero the atomicMax cell
//   k_scale : 32-block max|W| -> atomicMax (float-as-int, nonneg -> monotone)
//   k_quant : W_clip (fp32 math, stored as half, transposed k-major) + fp32 bias
//   k_main  : direct-conv SAD, HSUB2/HADD2(|.|), fp32 promote every 2 channels
//
// x (32,64,32,32) f32, W (128,64,3,3) f32, bits int32 -> out (32,128,32,32) f32

#define C_IN   64
#define H_IN   32
#define W_IN   32
#define M_OUT  128
#define KK     (C_IN * 9)   // 576
#define BATCH  32
#define CB     4            // channels per smem chunk

__device__ int   g_absmax_bits;
__device__ float g_bias[M_OUT];
__device__ __align__(16) __half g_Wh[KK * M_OUT];   // k-major, m contiguous, half

// ---------------------------------------------------------------------------
__global__ void k_init() { g_absmax_bits = 0; }

__global__ void k_scale(const float* __restrict__ W) {
    __shared__ float red[8];
    float m = 0.f;
    for (int i = blockIdx.x * 256 + threadIdx.x; i < M_OUT * KK; i += gridDim.x * 256)
        m = fmaxf(m, fabsf(W[i]));
    #pragma unroll
    for (int o = 16; o; o >>= 1) m = fmaxf(m, __shfl_xor_sync(0xffffffffu, m, o));
    if ((threadIdx.x & 31) == 0) red[threadIdx.x >> 5] = m;
    __syncthreads();
    if (threadIdx.x == 0) {
        float v = red[0];
        #pragma unroll
        for (int i = 1; i < 8; i++) v = fmaxf(v, red[i]);
        atomicMax(&g_absmax_bits, __float_as_int(v));   // nonneg floats: int-max == float-max
    }
}

// ---------------------------------------------------------------------------
__global__ void k_quant(const float* __restrict__ W, const int* __restrict__ bits_p) {
    const int m = blockIdx.x;
    const int bits = *bits_p;
    const float qmx = (float)((1 << (bits - 1)) - 1);
    const float qmn = -(float)(1 << (bits - 1));
    const float alpha = __int_as_float(g_absmax_bits);
    const float s = fmaxf(alpha / qmx, 1e-6f);

    float sum = 0.f;
    for (int k = threadIdx.x; k < KK; k += 256) {
        float w  = W[m * KK + k];
        float q  = rintf(w / s);                      // round half-to-even == jnp.round
        q        = fminf(fmaxf(q, qmn), qmx);
        float wc = q * s;
        g_Wh[k * M_OUT + m] = __float2half(wc);
        sum += fabsf(w - wc);
    }
    __shared__ float red[8];
    #pragma unroll
    for (int o = 16; o; o >>= 1) sum += __shfl_xor_sync(0xffffffffu, sum, o);
    if ((threadIdx.x & 31) == 0) red[threadIdx.x >> 5] = sum;
    __syncthreads();
    if (threadIdx.x == 0) {
        float t = 0.f;
        #pragma unroll
        for (int i = 0; i < 8; i++) t += red[i];
        g_bias[m] = -t;
    }
}

// ---------------------------------------------------------------------------
// K2: main SAD. grid (H_IN, BATCH) = 1024 blocks, 128 threads.
// thread (tm = tid>>3, tp = tid&7): m in [tm*8, +8), w in [tp*4, +4).
// fp16x2 packs 2 adjacent m; x scalar broadcast folds into .Hk_Hk selector.
// ---------------------------------------------------------------------------
__global__ void __launch_bounds__(128)
k_main(const float* __restrict__ x, float* __restrict__ out) {
    __shared__ __align__(16) __half sW[CB * 9][M_OUT];   // 9216 B
    __shared__ __align__(8)  __half sX[CB][3][40];       // 34 used, pad to 40

    const int h0  = blockIdx.x;
    const int b   = blockIdx.y;
    const int tid = threadIdx.x;
    const int tm  = tid >> 3;
    const int tp  = tid & 7;
    const int m0  = tm * 8;
    const int w0  = tp * 4;

    float accf[8][4];
    #pragma unroll
    for (int i = 0; i < 8; i++)
        #pragma unroll
        for (int j = 0; j < 4; j++) accf[i][j] = 0.f;

    half2 acc2[4][4];
    const half2 h2z = __float2half2_rn(0.f);
    #pragma unroll
    for (int p = 0; p < 4; p++)
        #pragma unroll
        for (int j = 0; j < 4; j++) acc2[p][j] = h2z;

    const float* xb_ptr = x + (size_t)b * C_IN * H_IN * W_IN;

    for (int c0 = 0; c0 < C_IN; c0 += CB) {
        // W chunk: CB*9*128 halves = 1152 uint2, 9 per thread
        {
            const uint2* gw = (const uint2*)(g_Wh + c0 * 9 * M_OUT);
            uint2*       sw = (uint2*)(&sW[0][0]);
            #pragma unroll
            for (int i = 0; i < 9; i++)
                sw[tid + i * 128] = gw[tid + i * 128];
        }
        // x chunk: CB x 3 x 34 halves, zero-padded halo, f32->f16 convert here
        for (int idx = tid; idx < CB * 3 * 34; idx += 128) {
            int ci  = idx / 102;
            int r   = idx - ci * 102;
            int dh  = r / 34;
            int cc  = r - dh * 34;
            int row = h0 + dh - 1;
            int col = cc - 1;
            float v = 0.f;
            if ((unsigned)row < H_IN && (unsigned)col < W_IN)
                v = xb_ptr[((c0 + ci) * H_IN + row) * W_IN + col];
            sX[ci][dh][cc] = __float2half(v);
        }
        __syncthreads();

        #pragma unroll
        for (int ci = 0; ci < CB; ci++) {
            // x registers: 3 rows x 3 aligned half2 (halves w0..w0+5)
            half2 xr[3][3];
            #pragma unroll
            for (int dh = 0; dh < 3; dh++) {
                xr[dh][0] = *(const half2*)&sX[ci][dh][w0];
                xr[dh][1] = *(const half2*)&sX[ci][dh][w0 + 2];
                xr[dh][2] = *(const half2*)&sX[ci][dh][w0 + 4];
            }

            #pragma unroll
            for (int t = 0; t < 9; t++) {
                const int dh = t / 3;
                const int dw = t - 3 * dh;
                uint4 wraw = *(const uint4*)&sW[ci * 9 + t][m0];  // 8 halves (m0..m0+7)
                half2 wp[4];
                wp[0] = *(half2*)&wraw.x; wp[1] = *(half2*)&wraw.y;
                wp[2] = *(half2*)&wraw.z; wp[3] = *(half2*)&wraw.w;
                #pragma unroll
                for (int j = 0; j < 4; j++) {
                    const int s = dw + j;              // 0..5, compile-time
                    half2 r = xr[dh][s >> 1];
                    half2 xbc = (s & 1) ? __high2half2(r) : __low2half2(r);
                    #pragma unroll
                    for (int p = 0; p < 4; p++)
                        acc2[p][j] = __hadd2(acc2[p][j],
                                             __habs2(__hsub2(wp[p], xbc)));
                }
            }

            // promote fp16 partials to fp32 every 2 channels (keeps err ~1e-4)
            if (ci & 1) {
                #pragma unroll
                for (int p = 0; p < 4; p++)
                    #pragma unroll
                    for (int j = 0; j < 4; j++) {
                        float2 f = __half22float2(acc2[p][j]);
                        accf[2 * p][j]     += f.x;
                        accf[2 * p + 1][j] += f.y;
                        acc2[p][j] = h2z;
                    }
            }
        }
        __syncthreads();
    }

    // epilogue: out[b][m][h0][w] = bias[m] - sum
    #pragma unroll
    for (int i = 0; i < 8; i++) {
        float bv = g_bias[m0 + i];
        float4 o;
        o.x = bv - accf[i][0];
        o.y = bv - accf[i][1];
        o.z = bv - accf[i][2];
        o.w = bv - accf[i][3];
        *(float4*)(out + (((size_t)b * M_OUT + (m0 + i)) * H_IN + h0) * W_IN + w0) = o;
    }
}

// ---------------------------------------------------------------------------
extern "C" void kernel_launch(void* const* d_in, const int* in_sizes, int n_in,
                              void* d_out, int out_size) {
    const float* x    = (const float*)d_in[0];
    const float* W    = (const float*)d_in[1];
    const int*   bits = (const int*)d_in[2];
    float*       out  = (float*)d_out;

    k_init<<<1, 1>>>();
    k_scale<<<32, 256>>>(W);
    k_quant<<<M_OUT, 256>>>(W, bits);
    dim3 grid(H_IN, BATCH);
    k_main<<<grid, 128>>>(x, out);
}